// round 3
// baseline (speedup 1.0000x reference)
#include <cuda_runtime.h>
#include <math.h>
#include <stdint.h>

// Problem constants (shapes are fixed for this problem instance; scratch is
// statically sized to them).
#define MAX_E     4194304
#define MAX_NOUT  524288
#define CCH       64            // channels
#define CV        32            // float2 per row

// -------- device scratch (no dynamic allocation allowed) --------
__device__ int g_counts [MAX_NOUT];
__device__ int g_cursor [MAX_NOUT];
__device__ int g_offsets[MAX_NOUT];
__device__ int g_bins   [MAX_E];
__device__ int g_blocksums[1024];

// -------- kernel 1: zero counters --------
__global__ void k_zero(int n_out) {
    int i = blockIdx.x * blockDim.x + threadIdx.x;
    if (i < n_out) g_counts[i] = 0;
}

// -------- kernel 2: histogram of valid edges per segment --------
__global__ void k_count(const int* __restrict__ src_ids,
                        const int* __restrict__ ntypes,
                        int E, int NT) {
    int e = blockIdx.x * blockDim.x + threadIdx.x;
    if (e >= E) return;
    const int* nt = ntypes + (size_t)e * NT;
    bool valid = true;
    for (int j = 0; j < NT; j++) valid &= (nt[j] >= 0);
    int s = src_ids[e];
    if (valid && (unsigned)s < (unsigned)MAX_NOUT) atomicAdd(&g_counts[s], 1);
}

// -------- kernel 3a: per-block exclusive scan (4096 elems / block) --------
__global__ void k_scan_blocks(int n) {
    __shared__ int sh[256];
    int tid  = threadIdx.x;
    int base = blockIdx.x * 4096 + tid * 16;
    int local[16];
    int sum = 0;
    #pragma unroll
    for (int i = 0; i < 16; i++) {
        local[i] = sum;
        int idx = base + i;
        sum += (idx < n) ? g_counts[idx] : 0;
    }
    sh[tid] = sum;
    __syncthreads();
    for (int off = 1; off < 256; off <<= 1) {
        int v = (tid >= off) ? sh[tid - off] : 0;
        __syncthreads();
        sh[tid] += v;
        __syncthreads();
    }
    int excl = sh[tid] - sum;
    #pragma unroll
    for (int i = 0; i < 16; i++) {
        int idx = base + i;
        if (idx < n) g_offsets[idx] = excl + local[i];
    }
    if (tid == 255) g_blocksums[blockIdx.x] = sh[255];
}

// -------- kernel 3b: exclusive scan of block sums (single block) --------
__global__ void k_scan_sums(int nb) {
    __shared__ int sh[1024];
    int tid = threadIdx.x;
    int v = (tid < nb) ? g_blocksums[tid] : 0;
    sh[tid] = v;
    __syncthreads();
    for (int off = 1; off < 1024; off <<= 1) {
        int w = (tid >= off) ? sh[tid - off] : 0;
        __syncthreads();
        sh[tid] += w;
        __syncthreads();
    }
    if (tid < nb) g_blocksums[tid] = sh[tid] - v;   // exclusive
}

// -------- kernel 3c: add block bases; seed scatter cursors --------
__global__ void k_add_base(int n) {
    int i = blockIdx.x * blockDim.x + threadIdx.x;
    if (i < n) {
        int o = g_offsets[i] + g_blocksums[i >> 12];
        g_offsets[i] = o;
        g_cursor[i]  = o;       // scatter cursor starts at segment base
    }
}

// -------- kernel 4: scatter edges into CSR bins --------
__global__ void k_scatter(const int* __restrict__ src_ids,
                          const int* __restrict__ tgt_ids,
                          const int* __restrict__ ntypes,
                          int E, int NT) {
    int e = blockIdx.x * blockDim.x + threadIdx.x;
    if (e >= E) return;
    const int* nt = ntypes + (size_t)e * NT;
    bool valid = true;
    for (int j = 0; j < NT; j++) valid &= (nt[j] >= 0);
    int s = src_ids[e];
    if (valid && (unsigned)s < (unsigned)MAX_NOUT) {
        int pos = atomicAdd(&g_cursor[s], 1);
        if ((unsigned)pos < (unsigned)MAX_E) g_bins[pos] = tgt_ids[e];
    }
}

// -------- kernel 5: one warp per segment, float2 per lane, 4-deep MLP --------
__global__ void k_pool(const float2* __restrict__ feat2,
                       float2* __restrict__ out2,
                       int n_out) {
    int gw   = (blockIdx.x * blockDim.x + threadIdx.x) >> 5;   // warp = segment
    int lane = threadIdx.x & 31;
    if (gw >= n_out) return;

    int start = g_offsets[gw];
    int cnt   = g_counts[gw];

    const float NEG_INF = -INFINITY;
    float2 acc = make_float2(NEG_INF, NEG_INF);

    int i = 0;
    // 4 independent gather chains per lane to raise MLP on the random reads
    for (; i + 3 < cnt; i += 4) {
        int t0 = __ldg(&g_bins[start + i]);
        int t1 = __ldg(&g_bins[start + i + 1]);
        int t2 = __ldg(&g_bins[start + i + 2]);
        int t3 = __ldg(&g_bins[start + i + 3]);
        float2 v0 = __ldg(&feat2[(size_t)t0 * CV + lane]);
        float2 v1 = __ldg(&feat2[(size_t)t1 * CV + lane]);
        float2 v2 = __ldg(&feat2[(size_t)t2 * CV + lane]);
        float2 v3 = __ldg(&feat2[(size_t)t3 * CV + lane]);
        acc.x = fmaxf(fmaxf(fmaxf(acc.x, v0.x), fmaxf(v1.x, v2.x)), v3.x);
        acc.y = fmaxf(fmaxf(fmaxf(acc.y, v0.y), fmaxf(v1.y, v2.y)), v3.y);
    }
    for (; i < cnt; i++) {
        int t0 = __ldg(&g_bins[start + i]);
        float2 v0 = __ldg(&feat2[(size_t)t0 * CV + lane]);
        acc.x = fmaxf(acc.x, v0.x); acc.y = fmaxf(acc.y, v0.y);
    }

    if (cnt == 0) acc = make_float2(0.0f, 0.0f);   // empty segment -> 0 (ref semantics)
    out2[(size_t)gw * CV + lane] = acc;
}

// -------- optional tail: tuple's second element (feat_depth+1) --------
__global__ void k_tail(float* __restrict__ out, const int* __restrict__ feat_depth,
                       int begin, int total) {
    int i = begin + blockIdx.x * blockDim.x + threadIdx.x;
    if (i < total) out[i] = (float)(feat_depth[0] + 1);
}

extern "C" void kernel_launch(void* const* d_in, const int* in_sizes, int n_in,
                              void* d_out, int out_size) {
    const float* feat    = (const float*)d_in[0];
    const int*   src_ids = (const int*)  d_in[1];
    const int*   tgt_ids = (const int*)  d_in[2];
    const int*   ntypes  = (const int*)  d_in[3];

    int E  = in_sizes[1];
    int NT = (E > 0) ? in_sizes[3] / E : 3;
    if (E > MAX_E) E = MAX_E;
    if (NT < 1) NT = 1;

    int n_out = out_size / CCH;               // 524288 for this instance
    if (n_out > MAX_NOUT) n_out = MAX_NOUT;

    // 1. zero counters
    k_zero<<<(n_out + 255) / 256, 256>>>(n_out);
    // 2. histogram
    k_count<<<(E + 255) / 256, 256>>>(src_ids, ntypes, E, NT);
    // 3. scan (block-local -> block sums -> add bases + cursor seed)
    int nb = (n_out + 4095) / 4096;
    k_scan_blocks<<<nb, 256>>>(n_out);
    k_scan_sums<<<1, 1024>>>(nb);
    k_add_base<<<(n_out + 255) / 256, 256>>>(n_out);
    // 4. scatter into CSR
    k_scatter<<<(E + 255) / 256, 256>>>(src_ids, tgt_ids, ntypes, E, NT);
    // 5. pool: one warp per segment, 8 warps per block
    int threads = 256;
    long long totalThreads = (long long)n_out * 32;
    int blocks = (int)((totalThreads + threads - 1) / threads);
    k_pool<<<blocks, threads>>>((const float2*)feat, (float2*)d_out, n_out);

    // If harness appended the tuple's scalar (feat_depth+1) after the matrix,
    // fill it; for out_size == n_out*C this launches nothing.
    int main_elems = n_out * CCH;
    if (out_size > main_elems && n_in >= 6) {
        int extra = out_size - main_elems;
        k_tail<<<(extra + 255) / 256, 256>>>((float*)d_out, (const int*)d_in[5],
                                             main_elems, out_size);
    }
}

// round 5
// speedup vs baseline: 1.0704x; 1.0704x over previous
#include <cuda_runtime.h>
#include <math.h>
#include <stdint.h>

#define MAX_E     4194304
#define MAX_NOUT  524288
#define CCH       64            // channels
#define CV4       16            // float4 per row

// -------- device scratch (no dynamic allocation allowed) --------
// NOTE: arrays accessed through int4* views MUST be 16B-aligned, otherwise the
// 128-bit LDG/STG traps (err715).
__device__ __align__(16) int g_vsrc   [MAX_E];     // valid ? src : -1
__device__ __align__(16) int g_bins   [MAX_E];
__device__ int g_counts [MAX_NOUT];
__device__ int g_cursor [MAX_NOUT];
__device__ int g_offsets[MAX_NOUT];
__device__ int g_total;              // atomic base for scan blocks

// -------- kernel 1: zero counters --------
__global__ void k_zero(int n_out) {
    int i = blockIdx.x * blockDim.x + threadIdx.x;
    if (i < n_out) g_counts[i] = 0;
    if (i == 0) g_total = 0;
}

// -------- kernel 2: histogram + validity fusion (4 edges/thread, int4) -----
__global__ void k_count_v4(const int4* __restrict__ src4,
                           const int4* __restrict__ nt4,
                           int E4) {                       // E/4
    int t = blockIdx.x * blockDim.x + threadIdx.x;
    if (t >= E4) return;
    int4 n0 = __ldg(&nt4[3 * t]);
    int4 n1 = __ldg(&nt4[3 * t + 1]);
    int4 n2 = __ldg(&nt4[3 * t + 2]);
    int4 s  = __ldg(&src4[t]);

    // edge k ntypes: packed 3 ints each across n0..n2
    int v0 = (n0.x >= 0 && n0.y >= 0 && n0.z >= 0) ? s.x : -1;
    int v1 = (n0.w >= 0 && n1.x >= 0 && n1.y >= 0) ? s.y : -1;
    int v2 = (n1.z >= 0 && n1.w >= 0 && n2.x >= 0) ? s.z : -1;
    int v3 = (n2.y >= 0 && n2.z >= 0 && n2.w >= 0) ? s.w : -1;

    ((int4*)g_vsrc)[t] = make_int4(v0, v1, v2, v3);
    if ((unsigned)v0 < (unsigned)MAX_NOUT) atomicAdd(&g_counts[v0], 1);
    if ((unsigned)v1 < (unsigned)MAX_NOUT) atomicAdd(&g_counts[v1], 1);
    if ((unsigned)v2 < (unsigned)MAX_NOUT) atomicAdd(&g_counts[v2], 1);
    if ((unsigned)v3 < (unsigned)MAX_NOUT) atomicAdd(&g_counts[v3], 1);
}

// scalar fallback (odd shapes)
__global__ void k_count_s(const int* __restrict__ src_ids,
                          const int* __restrict__ ntypes,
                          int E, int NT) {
    int e = blockIdx.x * blockDim.x + threadIdx.x;
    if (e >= E) return;
    const int* nt = ntypes + (size_t)e * NT;
    bool valid = true;
    for (int j = 0; j < NT; j++) valid &= (nt[j] >= 0);
    int s = src_ids[e];
    int v = (valid && (unsigned)s < (unsigned)MAX_NOUT) ? s : -1;
    g_vsrc[e] = v;
    if (v >= 0) atomicAdd(&g_counts[v], 1);
}

// -------- kernel 3: block scan + atomic base (offsets need not be ordered;
// any disjoint partition of bins is valid, max is order-independent) --------
__global__ void k_scan_atomic(int n) {
    __shared__ int sh[256];
    __shared__ int sh_base;
    int tid  = threadIdx.x;
    int base = blockIdx.x * 4096 + tid * 16;
    int local[16];
    int sum = 0;
    #pragma unroll
    for (int i = 0; i < 16; i++) {
        local[i] = sum;
        int idx = base + i;
        sum += (idx < n) ? g_counts[idx] : 0;
    }
    sh[tid] = sum;
    __syncthreads();
    for (int off = 1; off < 256; off <<= 1) {
        int v = (tid >= off) ? sh[tid - off] : 0;
        __syncthreads();
        sh[tid] += v;
        __syncthreads();
    }
    if (tid == 255) sh_base = atomicAdd(&g_total, sh[255]);
    __syncthreads();
    int excl = sh_base + sh[tid] - sum;
    #pragma unroll
    for (int i = 0; i < 16; i++) {
        int idx = base + i;
        if (idx < n) {
            int o = excl + local[i];
            g_offsets[idx] = o;
            g_cursor[idx]  = o;
        }
    }
}

// -------- kernel 4: scatter edges into CSR bins (4 edges/thread) --------
__global__ void k_scatter_v4(const int4* __restrict__ tgt4, int E4) {
    int t = blockIdx.x * blockDim.x + threadIdx.x;
    if (t >= E4) return;
    int4 v  = ((const int4*)g_vsrc)[t];
    int4 tg = __ldg(&tgt4[t]);
    if (v.x >= 0) { int p = atomicAdd(&g_cursor[v.x], 1); if ((unsigned)p < (unsigned)MAX_E) g_bins[p] = tg.x; }
    if (v.y >= 0) { int p = atomicAdd(&g_cursor[v.y], 1); if ((unsigned)p < (unsigned)MAX_E) g_bins[p] = tg.y; }
    if (v.z >= 0) { int p = atomicAdd(&g_cursor[v.z], 1); if ((unsigned)p < (unsigned)MAX_E) g_bins[p] = tg.z; }
    if (v.w >= 0) { int p = atomicAdd(&g_cursor[v.w], 1); if ((unsigned)p < (unsigned)MAX_E) g_bins[p] = tg.w; }
}

__global__ void k_scatter_s(const int* __restrict__ tgt_ids, int E) {
    int e = blockIdx.x * blockDim.x + threadIdx.x;
    if (e >= E) return;
    int v = g_vsrc[e];
    if (v >= 0) {
        int p = atomicAdd(&g_cursor[v], 1);
        if ((unsigned)p < (unsigned)MAX_E) g_bins[p] = tgt_ids[e];
    }
}

// -------- kernel 5: one warp per segment; two half-warps, float4/lane ------
__global__ void k_pool(const float4* __restrict__ feat4,
                       float4* __restrict__ out4,
                       int n_out) {
    int gw    = (blockIdx.x * blockDim.x + threadIdx.x) >> 5;   // warp = segment
    int lane  = threadIdx.x & 31;
    int half  = lane >> 4;        // 0 or 1: which edge of the pair
    int qlane = lane & 15;        // float4 index within the 64-ch row
    if (gw >= n_out) return;

    int start = g_offsets[gw];
    int cnt   = g_counts[gw];

    const float NI = -INFINITY;
    float4 acc = make_float4(NI, NI, NI, NI);

    // 4 edges in flight per warp (2 per half-warp), converged loop
    int i = 0;
    for (; i + 3 < cnt; i += 4) {
        int e0 = __ldg(&g_bins[start + i + half]);
        int e1 = __ldg(&g_bins[start + i + 2 + half]);
        float4 a = __ldg(&feat4[(size_t)e0 * CV4 + qlane]);
        float4 b = __ldg(&feat4[(size_t)e1 * CV4 + qlane]);
        acc.x = fmaxf(acc.x, fmaxf(a.x, b.x));
        acc.y = fmaxf(acc.y, fmaxf(a.y, b.y));
        acc.z = fmaxf(acc.z, fmaxf(a.z, b.z));
        acc.w = fmaxf(acc.w, fmaxf(a.w, b.w));
    }
    for (; i < cnt; i += 2) {
        int e = i + half;
        if (e < cnt) {
            int t0 = __ldg(&g_bins[start + e]);
            float4 a = __ldg(&feat4[(size_t)t0 * CV4 + qlane]);
            acc.x = fmaxf(acc.x, a.x);
            acc.y = fmaxf(acc.y, a.y);
            acc.z = fmaxf(acc.z, a.z);
            acc.w = fmaxf(acc.w, a.w);
        }
    }

    // merge the two half-warp partial maxima (lane <-> lane^16)
    acc.x = fmaxf(acc.x, __shfl_xor_sync(0xffffffffu, acc.x, 16));
    acc.y = fmaxf(acc.y, __shfl_xor_sync(0xffffffffu, acc.y, 16));
    acc.z = fmaxf(acc.z, __shfl_xor_sync(0xffffffffu, acc.z, 16));
    acc.w = fmaxf(acc.w, __shfl_xor_sync(0xffffffffu, acc.w, 16));

    if (cnt == 0) acc = make_float4(0.0f, 0.0f, 0.0f, 0.0f);
    if (half == 0) out4[(size_t)gw * CV4 + qlane] = acc;
}

// -------- optional tail: tuple's second element (feat_depth+1) --------
__global__ void k_tail(float* __restrict__ out, const int* __restrict__ feat_depth,
                       int begin, int total) {
    int i = begin + blockIdx.x * blockDim.x + threadIdx.x;
    if (i < total) out[i] = (float)(feat_depth[0] + 1);
}

extern "C" void kernel_launch(void* const* d_in, const int* in_sizes, int n_in,
                              void* d_out, int out_size) {
    const float* feat    = (const float*)d_in[0];
    const int*   src_ids = (const int*)  d_in[1];
    const int*   tgt_ids = (const int*)  d_in[2];
    const int*   ntypes  = (const int*)  d_in[3];

    int E  = in_sizes[1];
    int NT = (E > 0) ? in_sizes[3] / E : 3;
    if (E > MAX_E) E = MAX_E;
    if (NT < 1) NT = 1;

    int n_out = out_size / CCH;
    if (n_out > MAX_NOUT) n_out = MAX_NOUT;

    // 1. zero counters
    k_zero<<<(n_out + 255) / 256, 256>>>(n_out);

    // 2. histogram + validity fusion
    bool vec = (NT == 3) && (E % 4 == 0) &&
               ((((uintptr_t)src_ids | (uintptr_t)tgt_ids | (uintptr_t)ntypes) & 15u) == 0);
    if (vec) {
        int E4 = E / 4;
        k_count_v4<<<(E4 + 255) / 256, 256>>>((const int4*)src_ids,
                                              (const int4*)ntypes, E4);
    } else {
        k_count_s<<<(E + 255) / 256, 256>>>(src_ids, ntypes, E, NT);
    }

    // 3. single-kernel scan with atomic block base
    int nb = (n_out + 4095) / 4096;
    k_scan_atomic<<<nb, 256>>>(n_out);

    // 4. scatter into CSR
    if (vec) {
        int E4 = E / 4;
        k_scatter_v4<<<(E4 + 255) / 256, 256>>>((const int4*)tgt_ids, E4);
    } else {
        k_scatter_s<<<(E + 255) / 256, 256>>>(tgt_ids, E);
    }

    // 5. pool: one warp per segment, 8 warps per block
    int threads = 256;
    long long totalThreads = (long long)n_out * 32;
    int blocks = (int)((totalThreads + threads - 1) / threads);
    k_pool<<<blocks, threads>>>((const float4*)feat, (float4*)d_out, n_out);

    // tuple scalar tail (no-op for out_size == n_out*C)
    int main_elems = n_out * CCH;
    if (out_size > main_elems && n_in >= 6) {
        int extra = out_size - main_elems;
        k_tail<<<(extra + 255) / 256, 256>>>((float*)d_out, (const int*)d_in[5],
                                             main_elems, out_size);
    }
}